// round 6
// baseline (speedup 1.0000x reference)
#include <cuda_runtime.h>

// DropBlock, 2 kernels + PDL overlap:
//   mask_kernel: bit-parallel separable 7x7 backward dilation of (u < GAMMA),
//                writes mask*scale to g_ms4 (float4 stores), triggers PDL.
//   apply_kernel: PDL secondary; front-batches 8 float4 loads of x BEFORE
//                cudaGridDependencySynchronize() (MLP=8), then masks+stores.
// GAMMA = 0.1/49 * (56^2/50^2) = 0.00256 exactly.

#define H 56
#define W 56
#define HW 3136          // 56*56
#define HW4 784          // HW/4
#define GAMMA 0.00256f
#define THREADS 256
#define V4_PER_THREAD 8
#define V4_PER_CTA (THREADS * V4_PER_THREAD)   // 2048

// mask * scale, packed for float4 loads (12.5 KB, L1/L2 resident)
__device__ float4 g_ms4[HW4];

__global__ void __launch_bounds__(256) mask_kernel(const float* __restrict__ u) {
    __shared__ float su[H * 57];           // stride-57 pad
    __shared__ unsigned long long rowd[H];
    __shared__ unsigned long long dil[H];
    __shared__ int pc[H];
    __shared__ float s_scale;
    const int tid = threadIdx.x;

    // coalesced load of u into padded shared
    #pragma unroll
    for (int j = 0; j < 13; ++j) {
        const int s = tid + j * 256;
        if (s < HW) su[(s / W) * 57 + (s % W)] = u[s];
    }
    __syncthreads();

    // row-wise backward dilation (width 7) as bit ops
    if (tid < H) {
        unsigned long long s = 0ULL;
        #pragma unroll
        for (int w = 0; w < W; ++w)
            s |= (unsigned long long)(su[tid * 57 + w] < GAMMA) << w;
        unsigned long long a = s | (s << 1);     // {0,1}
        unsigned long long b = a | (a << 2);     // {0..3}
        unsigned long long c = b | (b << 3);     // {0..6}
        rowd[tid] = c & ((1ULL << W) - 1ULL);
    }
    __syncthreads();

    // column-wise rolling OR over rows h-6..h + popcount
    if (tid < H) {
        const int h0 = tid - 6 < 0 ? 0 : tid - 6;
        unsigned long long d = 0ULL;
        for (int h = h0; h <= tid; ++h) d |= rowd[h];
        dil[tid] = d;
        pc[tid] = __popcll(d);
    }
    __syncthreads();

    if (tid == 0) {
        int tot = 0;
        #pragma unroll
        for (int h = 0; h < H; ++h) tot += pc[h];
        s_scale = (float)HW / (float)(HW - tot);
    }
    __syncthreads();

    // write mask*scale as float4 (784 stores over 256 threads)
    const float scale = s_scale;
    #pragma unroll
    for (int j = 0; j < 4; ++j) {
        const int s4 = tid + j * 256;
        if (s4 < HW4) {
            const int h = s4 / 14;               // 14 float4 per row
            const int w0 = (s4 % 14) * 4;
            const unsigned long long bits = dil[h] >> w0;
            float4 mk;
            mk.x = (bits & 1ULL) ? 0.0f : scale;
            mk.y = (bits & 2ULL) ? 0.0f : scale;
            mk.z = (bits & 4ULL) ? 0.0f : scale;
            mk.w = (bits & 8ULL) ? 0.0f : scale;
            g_ms4[s4] = mk;
        }
    }
    __threadfence();
    __syncthreads();
    cudaTriggerProgrammaticLaunchCompletion();
}

__global__ void __launch_bounds__(THREADS) apply_kernel(
    const float4* __restrict__ x, float4* __restrict__ out) {
    const int base = blockIdx.x * V4_PER_CTA + threadIdx.x;

    // front-batch all 8 loads of x before depending on mask_kernel (MLP=8)
    float4 v[V4_PER_THREAD];
    #pragma unroll
    for (int k = 0; k < V4_PER_THREAD; ++k)
        v[k] = __ldcs(&x[base + k * THREADS]);

    cudaGridDependencySynchronize();

    int s4 = base % HW4;                         // incremental wrap, no per-iter %
    #pragma unroll
    for (int k = 0; k < V4_PER_THREAD; ++k) {
        const float4 mk = g_ms4[s4];
        v[k].x *= mk.x; v[k].y *= mk.y; v[k].z *= mk.z; v[k].w *= mk.w;
        __stcs(&out[base + k * THREADS], v[k]);
        s4 += THREADS;
        if (s4 >= HW4) s4 -= HW4;
    }
}

extern "C" void kernel_launch(void* const* d_in, const int* in_sizes, int n_in,
                              void* d_out, int out_size) {
    const float* x = (const float*)d_in[0];   // (32,256,56,56) f32
    const float* u = (const float*)d_in[1];   // (56,56) f32

    mask_kernel<<<1, 256>>>(u);

    // 6,422,528 float4 = 3136 CTAs * 256 thr * 8
    const int n4 = out_size / 4;

    cudaLaunchConfig_t cfg = {};
    cfg.gridDim = dim3(n4 / V4_PER_CTA, 1, 1);
    cfg.blockDim = dim3(THREADS, 1, 1);
    cfg.dynamicSmemBytes = 0;
    cfg.stream = 0;
    cudaLaunchAttribute attr[1];
    attr[0].id = cudaLaunchAttributeProgrammaticStreamSerialization;
    attr[0].val.programmaticStreamSerializationAllowed = 1;
    cfg.attrs = attr;
    cfg.numAttrs = 1;
    cudaLaunchKernelEx(&cfg, apply_kernel, (const float4*)x, (float4*)d_out);
}

// round 8
// speedup vs baseline: 1.0437x; 1.0437x over previous
#include <cuda_runtime.h>

// DropBlock, 2 kernels + PDL overlap:
//   mask_kernel (64 thr, 2 barriers): bit-parallel separable 7x7 backward
//     dilation of (u < GAMMA). Each of 56 threads loads its 224B row of u as
//     14 aligned float4s, builds a 56-bit word, dilates; column pass is a
//     rolling OR over shared row-words; scale summed redundantly per thread.
//   apply_kernel (PDL secondary): prefetches 4 float4s of x before
//     cudaGridDependencySynchronize(), then masks + streaming-stores.
// GAMMA = 0.1/49 * (56^2/50^2) = 0.00256 exactly.
// (R7 was an infra failure; this is the same candidate, re-benched.)

#define H 56
#define W 56
#define HW 3136          // 56*56
#define HW4 784          // HW/4
#define GAMMA 0.00256f
#define THREADS 256
#define V4_PER_THREAD 4
#define V4_PER_CTA (THREADS * V4_PER_THREAD)   // 1024

// mask * scale, packed for float4 loads (12.5 KB, L2 resident)
__device__ float4 g_ms4[HW4];

__global__ void __launch_bounds__(64) mask_kernel(const float4* __restrict__ u4) {
    __shared__ unsigned long long rowd[H];
    __shared__ int pc[H];
    const int tid = threadIdx.x;

    unsigned long long dil = 0ULL;

    // ── row phase: load own row (14 aligned float4), threshold, dilate ──
    if (tid < H) {
        float4 r[14];
        #pragma unroll
        for (int j = 0; j < 14; ++j) r[j] = __ldg(&u4[tid * 14 + j]);
        unsigned long long s = 0ULL;
        #pragma unroll
        for (int j = 0; j < 14; ++j) {
            const int w = j * 4;
            s |= (unsigned long long)(r[j].x < GAMMA) << (w + 0);
            s |= (unsigned long long)(r[j].y < GAMMA) << (w + 1);
            s |= (unsigned long long)(r[j].z < GAMMA) << (w + 2);
            s |= (unsigned long long)(r[j].w < GAMMA) << (w + 3);
        }
        unsigned long long a = s | (s << 1);     // shifts {0,1}
        unsigned long long b = a | (a << 2);     // shifts {0..3}
        unsigned long long c = b | (b << 3);     // shifts {0..6}
        rowd[tid] = c & ((1ULL << W) - 1ULL);
    }
    __syncthreads();

    // ── column phase: rolling OR over rows h-6..h, popcount ──
    if (tid < H) {
        const int h0 = tid - 6 < 0 ? 0 : tid - 6;
        unsigned long long d = 0ULL;
        for (int h = h0; h <= tid; ++h) d |= rowd[h];
        dil = d;
        pc[tid] = __popcll(d);
    }
    __syncthreads();

    // ── scale (redundant per-thread sum, no broadcast barrier) + write ──
    if (tid < H) {
        int tot = 0;
        #pragma unroll
        for (int h = 0; h < H; ++h) tot += pc[h];
        const float scale = (float)HW / (float)(HW - tot);
        #pragma unroll
        for (int j = 0; j < 14; ++j) {
            const unsigned long long bits = dil >> (j * 4);
            float4 mk;
            mk.x = (bits & 1ULL) ? 0.0f : scale;
            mk.y = (bits & 2ULL) ? 0.0f : scale;
            mk.z = (bits & 4ULL) ? 0.0f : scale;
            mk.w = (bits & 8ULL) ? 0.0f : scale;
            g_ms4[tid * 14 + j] = mk;
        }
    }
    __threadfence();
    cudaTriggerProgrammaticLaunchCompletion();
}

__global__ void __launch_bounds__(THREADS) apply_kernel(
    const float4* __restrict__ x, float4* __restrict__ out) {
    const int base = blockIdx.x * V4_PER_CTA + threadIdx.x;

    // front-batch all 4 x loads before depending on mask_kernel
    float4 v[V4_PER_THREAD];
    #pragma unroll
    for (int k = 0; k < V4_PER_THREAD; ++k)
        v[k] = __ldcs(&x[base + k * THREADS]);

    cudaGridDependencySynchronize();

    int s4 = base % HW4;                         // incremental wrap
    #pragma unroll
    for (int k = 0; k < V4_PER_THREAD; ++k) {
        const float4 mk = g_ms4[s4];
        v[k].x *= mk.x; v[k].y *= mk.y; v[k].z *= mk.z; v[k].w *= mk.w;
        __stcs(&out[base + k * THREADS], v[k]);
        s4 += THREADS;
        if (s4 >= HW4) s4 -= HW4;
    }
}

extern "C" void kernel_launch(void* const* d_in, const int* in_sizes, int n_in,
                              void* d_out, int out_size) {
    const float* x = (const float*)d_in[0];   // (32,256,56,56) f32
    const float* u = (const float*)d_in[1];   // (56,56) f32

    mask_kernel<<<1, 64>>>((const float4*)u);

    // 6,422,528 float4 = 6272 CTAs * 256 thr * 4
    const int n4 = out_size / 4;

    cudaLaunchConfig_t cfg = {};
    cfg.gridDim = dim3(n4 / V4_PER_CTA, 1, 1);
    cfg.blockDim = dim3(THREADS, 1, 1);
    cfg.dynamicSmemBytes = 0;
    cfg.stream = 0;
    cudaLaunchAttribute attr[1];
    attr[0].id = cudaLaunchAttributeProgrammaticStreamSerialization;
    attr[0].val.programmaticStreamSerializationAllowed = 1;
    cfg.attrs = attr;
    cfg.numAttrs = 1;
    cudaLaunchKernelEx(&cfg, apply_kernel, (const float4*)x, (float4*)d_out);
}